// round 13
// baseline (speedup 1.0000x reference)
#include <cuda_runtime.h>
#include <cuda_bf16.h>

// Cosine similarity per row: out[i] = dot(q_i, d_i) / (||q_i|| * ||d_i||)
// N = 262144 rows, D = 256 fp32.
// Combines the session's two measured winners:
//  - 256-thread blocks, 8 warps x 4 iterations over a contiguous 32-row
//    chunk (best DRAM efficiency: 88.3%, 7.00 TB/s in round 7)
//  - block results staged in smem, flushed as one coalesced 128B store
//    (round 11: removes partial-sector writeback, ~0.3us)
// One row per warp per iteration, 4 front-batched LDG.128 + streaming hints.

#define D_DIM 256
#define D4 (D_DIM / 4)
#define THREADS_PER_BLOCK 256
#define WARPS_PER_BLOCK (THREADS_PER_BLOCK / 32)   // 8
#define ITERS 4
#define ROWS_PER_BLOCK (WARPS_PER_BLOCK * ITERS)   // 32

__device__ __forceinline__ float row_score(const float4* __restrict__ qr,
                                           const float4* __restrict__ dr,
                                           int lane) {
    // Front-batch the 4 LDG.128 for this row, interleaving q/d streams.
    float4 qa = __ldcs(qr + lane);
    float4 da = __ldcs(dr + lane);
    float4 qb = __ldcs(qr + lane + 32);
    float4 db = __ldcs(dr + lane + 32);

    float dot = qa.x * da.x + qa.y * da.y + qa.z * da.z + qa.w * da.w
              + qb.x * db.x + qb.y * db.y + qb.z * db.z + qb.w * db.w;
    float qq  = qa.x * qa.x + qa.y * qa.y + qa.z * qa.z + qa.w * qa.w
              + qb.x * qb.x + qb.y * qb.y + qb.z * qb.z + qb.w * qb.w;
    float dd  = da.x * da.x + da.y * da.y + da.z * da.z + da.w * da.w
              + db.x * db.x + db.y * db.y + db.z * db.z + db.w * db.w;

    #pragma unroll
    for (int off = 16; off > 0; off >>= 1) {
        dot += __shfl_xor_sync(0xFFFFFFFFu, dot, off);
        qq  += __shfl_xor_sync(0xFFFFFFFFu, qq,  off);
        dd  += __shfl_xor_sync(0xFFFFFFFFu, dd,  off);
    }

    return dot * rsqrtf(qq * dd);
}

__global__ __launch_bounds__(THREADS_PER_BLOCK, 8)
void cosine_sim_kernel(const float4* __restrict__ q4,
                       const float4* __restrict__ d4,
                       float* __restrict__ out,
                       int n_rows) {
    __shared__ float results[ROWS_PER_BLOCK];

    const int lane = threadIdx.x & 31;
    const int warp = threadIdx.x >> 5;
    const int block_row0 = blockIdx.x * ROWS_PER_BLOCK;
    const int base = block_row0 + warp;

    if (block_row0 + ROWS_PER_BLOCK <= n_rows) {
        // Full block: branch-free, pointers advance by increment.
        int row = base;
        const float4* qr = q4 + (size_t)row * D4;
        const float4* dr = d4 + (size_t)row * D4;
        #pragma unroll 1
        for (int i = 0; i < ITERS; i++) {
            float s = row_score(qr, dr, lane);
            if (lane == 0) results[row - block_row0] = s;
            row += WARPS_PER_BLOCK;
            qr  += WARPS_PER_BLOCK * D4;
            dr  += WARPS_PER_BLOCK * D4;
        }
        __syncthreads();
        // One coalesced 128B store for the whole block's results.
        if (threadIdx.x < ROWS_PER_BLOCK) {
            __stcs(out + block_row0 + threadIdx.x, results[threadIdx.x]);
        }
    } else {
        // Ragged tail block: per-row bounds + direct stores.
        #pragma unroll 1
        for (int i = 0; i < ITERS; i++) {
            const int row = base + i * WARPS_PER_BLOCK;
            if (row >= n_rows) break;
            float s = row_score(q4 + (size_t)row * D4, d4 + (size_t)row * D4, lane);
            if (lane == 0) __stcs(out + row, s);
        }
    }
}

extern "C" void kernel_launch(void* const* d_in, const int* in_sizes, int n_in,
                              void* d_out, int out_size) {
    const float4* q = (const float4*)d_in[0];
    const float4* d = (const float4*)d_in[1];
    float* out = (float*)d_out;

    const int n_rows = in_sizes[0] / D_DIM;
    const int blocks = (n_rows + ROWS_PER_BLOCK - 1) / ROWS_PER_BLOCK;

    cosine_sim_kernel<<<blocks, THREADS_PER_BLOCK>>>(q, d, out, n_rows);
}

// round 14
// speedup vs baseline: 1.0358x; 1.0358x over previous
#include <cuda_runtime.h>
#include <cuda_bf16.h>

// Cosine similarity per row: out[i] = dot(q_i, d_i) / (||q_i|| * ||d_i||)
// N = 262144 rows, D = 256 fp32.
// FINAL (session-best, round 11 config): classic launch; each block owns a
// contiguous 32-row chunk as 16 warps x 2 iterations (512-thread blocks),
// one row per warp per iteration with 4 front-batched LDG.128 + streaming
// load hints. Block results staged in smem and flushed as one coalesced
// 128B store per block (avoids partial-sector writeback amplification).
// Measured: 77.98us bench / 87% DRAM — at the practical HBM ceiling for
// this irreducible 537MB stream.

#define D_DIM 256
#define D4 (D_DIM / 4)
#define THREADS_PER_BLOCK 512
#define WARPS_PER_BLOCK (THREADS_PER_BLOCK / 32)   // 16
#define ITERS 2
#define ROWS_PER_BLOCK (WARPS_PER_BLOCK * ITERS)   // 32

__device__ __forceinline__ float row_score(const float4* __restrict__ qr,
                                           const float4* __restrict__ dr,
                                           int lane) {
    // Front-batch the 4 LDG.128 for this row, interleaving q/d streams.
    float4 qa = __ldcs(qr + lane);
    float4 da = __ldcs(dr + lane);
    float4 qb = __ldcs(qr + lane + 32);
    float4 db = __ldcs(dr + lane + 32);

    float dot = qa.x * da.x + qa.y * da.y + qa.z * da.z + qa.w * da.w
              + qb.x * db.x + qb.y * db.y + qb.z * db.z + qb.w * db.w;
    float qq  = qa.x * qa.x + qa.y * qa.y + qa.z * qa.z + qa.w * qa.w
              + qb.x * qb.x + qb.y * qb.y + qb.z * qb.z + qb.w * qb.w;
    float dd  = da.x * da.x + da.y * da.y + da.z * da.z + da.w * da.w
              + db.x * db.x + db.y * db.y + db.z * db.z + db.w * db.w;

    #pragma unroll
    for (int off = 16; off > 0; off >>= 1) {
        dot += __shfl_xor_sync(0xFFFFFFFFu, dot, off);
        qq  += __shfl_xor_sync(0xFFFFFFFFu, qq,  off);
        dd  += __shfl_xor_sync(0xFFFFFFFFu, dd,  off);
    }

    return dot * rsqrtf(qq * dd);
}

__global__ __launch_bounds__(THREADS_PER_BLOCK, 4)
void cosine_sim_kernel(const float4* __restrict__ q4,
                       const float4* __restrict__ d4,
                       float* __restrict__ out,
                       int n_rows) {
    __shared__ float results[ROWS_PER_BLOCK];

    const int lane = threadIdx.x & 31;
    const int warp = threadIdx.x >> 5;
    const int block_row0 = blockIdx.x * ROWS_PER_BLOCK;
    const int base = block_row0 + warp;

    if (block_row0 + ROWS_PER_BLOCK <= n_rows) {
        // Full block: branch-free, pointers advance by increment.
        int row = base;
        const float4* qr = q4 + (size_t)row * D4;
        const float4* dr = d4 + (size_t)row * D4;
        #pragma unroll 1
        for (int i = 0; i < ITERS; i++) {
            float s = row_score(qr, dr, lane);
            if (lane == 0) results[row - block_row0] = s;
            row += WARPS_PER_BLOCK;
            qr  += WARPS_PER_BLOCK * D4;
            dr  += WARPS_PER_BLOCK * D4;
        }
        __syncthreads();
        // One coalesced 128B store for the whole block's results.
        if (threadIdx.x < ROWS_PER_BLOCK) {
            __stcs(out + block_row0 + threadIdx.x, results[threadIdx.x]);
        }
    } else {
        // Ragged tail block: per-row bounds + direct stores.
        #pragma unroll 1
        for (int i = 0; i < ITERS; i++) {
            const int row = base + i * WARPS_PER_BLOCK;
            if (row >= n_rows) break;
            float s = row_score(q4 + (size_t)row * D4, d4 + (size_t)row * D4, lane);
            if (lane == 0) __stcs(out + row, s);
        }
    }
}

extern "C" void kernel_launch(void* const* d_in, const int* in_sizes, int n_in,
                              void* d_out, int out_size) {
    const float4* q = (const float4*)d_in[0];
    const float4* d = (const float4*)d_in[1];
    float* out = (float*)d_out;

    const int n_rows = in_sizes[0] / D_DIM;
    const int blocks = (n_rows + ROWS_PER_BLOCK - 1) / ROWS_PER_BLOCK;

    cosine_sim_kernel<<<blocks, THREADS_PER_BLOCK>>>(q, d, out, n_rows);
}